// round 14
// baseline (speedup 1.0000x reference)
#include <cuda_runtime.h>
#include <cuda_fp16.h>
#include <cstdint>

#define N_NODES 50000
#define NP      50048            // padded to 391*128
#define N_EDGES 800000
#define EMB     128
#define HID     256
#define EDGE_F  16
#define NLAYERS 5
#define BN_EPS  1e-5f

// ================= device scratch (static, no allocation) =================
__device__ __half g_ah[NP * EMB];   // x-split hi (GEMM0 A)
__device__ __half g_al[NP * EMB];   // x-split lo (GEMM0 A residual)
__device__ __half g_hh[NP * HID];   // hidden (GEMM2 A, single fp16 term)
__device__ __half g_h[NP * EMB];    // node features (fp16)
__device__ float g_agg[NP * EMB];   // layer out (pre-BN, fp32)
__device__ __half g_wxh[EMB * EMB];            // weights: fp16, [N][K] transposed
__device__ __half g_w1h[NLAYERS * HID * EMB];
__device__ __half g_w2h[NLAYERS * EMB * HID];
__device__ float g_S[N_NODES * EDGE_F];
__device__ int   g_deg[N_NODES];
__device__ int   g_fill[N_NODES];
__device__ int   g_rowptr[N_NODES + 1];
__device__ int   g_csr_src[N_EDGES];
__device__ int   g_csr_eid[N_EDGES];
__device__ float g_bsum[NLAYERS * EMB];
__device__ float g_bsq[NLAYERS * EMB];

__device__ __forceinline__ void split_f16(float v, __half& hi, __half& lo) {
    hi = __float2half_rn(v);
    lo = __float2half_rn(v - __half2float(hi));
}

#define LDSM4(r0, r1, r2, r3, addr) \
    asm volatile("ldmatrix.sync.aligned.m8n8.x4.shared.b16 {%0,%1,%2,%3}, [%4];" \
                 : "=r"(r0), "=r"(r1), "=r"(r2), "=r"(r3) : "r"(addr))

#define MMA16816(d, a, b0, b1) \
    asm volatile("mma.sync.aligned.m16n8k16.row.col.f32.f16.f16.f32 " \
                 "{%0,%1,%2,%3},{%4,%5,%6,%7},{%8,%9},{%0,%1,%2,%3};" \
                 : "+f"((d)[0]), "+f"((d)[1]), "+f"((d)[2]), "+f"((d)[3]) \
                 : "r"((a)[0]), "r"((a)[1]), "r"((a)[2]), "r"((a)[3]), \
                   "r"(b0), "r"(b1))

#define CP_ASYNC16(dst, src) \
    asm volatile("cp.async.cg.shared.global [%0], [%1], 16;" :: "r"(dst), "l"(src))
#define CP_COMMIT() asm volatile("cp.async.commit_group;")
#define CP_WAIT1()  asm volatile("cp.async.wait_group 1;")
#define CP_WAIT0()  asm volatile("cp.async.wait_group 0;")

#define ACC_ROW(acc, raw) do { \
    const __half2* _p = (const __half2*)&(raw); \
    float2 _a = __half22float2(_p[0]); \
    float2 _b = __half22float2(_p[1]); \
    (acc).x += _a.x; (acc).y += _a.y; (acc).z += _b.x; (acc).w += _b.y; \
} while (0)

// ================= combined prep =================
__global__ void k_prep(const float* __restrict__ Wx, const float* __restrict__ W1,
                       const float* __restrict__ W2) {
    int i = blockIdx.x * blockDim.x + threadIdx.x;
    if (i < N_NODES) { g_deg[i] = 0; g_fill[i] = 0; }
    if (i < NLAYERS * EMB) { g_bsum[i] = 0.f; g_bsq[i] = 0.f; }
    if (i < EMB * EMB) {
        int k = i / EMB, n = i - k * EMB;
        g_wxh[n * EMB + k] = __float2half_rn(Wx[i]);
    }
    if (i < NLAYERS * EMB * HID) {
        int l = i / (EMB * HID);
        int r = i - l * (EMB * HID);
        int k = r / HID, n = r - k * HID;
        g_w1h[l * EMB * HID + n * EMB + k] = __float2half_rn(W1[i]);
    }
    if (i < NLAYERS * HID * EMB) {
        int l = i / (HID * EMB);
        int r = i - l * (HID * EMB);
        int k = r / EMB, n = r - k * EMB;
        g_w2h[l * HID * EMB + n * HID + k] = __float2half_rn(W2[i]);
    }
}

__global__ void k_hist(const int* __restrict__ ei) {
    int e = blockIdx.x * blockDim.x + threadIdx.x;
    if (e < N_EDGES) atomicAdd(&g_deg[ei[N_EDGES + e]], 1);
}
__global__ void k_scan() {
    const int NT = 1024;
    const int CH = (N_NODES + NT - 1) / NT;
    __shared__ int sh[NT];
    int t = threadIdx.x;
    int s0 = t * CH, s1 = s0 + CH;
    if (s1 > N_NODES) s1 = N_NODES;
    int s = 0;
    for (int i = s0; i < s1; i++) s += g_deg[i];
    sh[t] = s;
    __syncthreads();
    for (int off = 1; off < NT; off <<= 1) {
        int v = (t >= off) ? sh[t - off] : 0;
        __syncthreads();
        sh[t] += v;
        __syncthreads();
    }
    int run = sh[t] - s;
    for (int i = s0; i < s1; i++) { g_rowptr[i] = run; run += g_deg[i]; }
    if (t == NT - 1) g_rowptr[N_NODES] = sh[NT - 1];
}
__global__ void k_fill(const int* __restrict__ ei) {
    int e = blockIdx.x * blockDim.x + threadIdx.x;
    if (e >= N_EDGES) return;
    int src = ei[e];
    int dst = ei[N_EDGES + e];
    int pos = g_rowptr[dst] + atomicAdd(&g_fill[dst], 1);
    g_csr_src[pos] = src;
    g_csr_eid[pos] = e;
}
__global__ void k_ssum(const float* __restrict__ ea) {
    int gw = (blockIdx.x * blockDim.x + threadIdx.x) >> 5;
    int lane = threadIdx.x & 31;
    if (gw >= N_NODES || lane >= EDGE_F) return;
    int beg = g_rowptr[gw], end = g_rowptr[gw + 1];
    float s = 0.f;
    for (int e = beg; e < end; e++)
        s += ea[(size_t)g_csr_eid[e] * EDGE_F + lane];
    g_S[gw * EDGE_F + lane] = s;
}

// x -> fp16 hi/lo split (float4 vectorized)
__global__ void k_xsplit(const float* __restrict__ x) {
    int i = blockIdx.x * blockDim.x + threadIdx.x;
    if (i >= N_NODES * EMB / 4) return;
    float4 v = __ldg(&((const float4*)x)[i]);
    __half h0, l0, h1, l1, h2, l2, h3, l3;
    split_f16(v.x, h0, l0); split_f16(v.y, h1, l1);
    split_f16(v.z, h2, l2); split_f16(v.w, h3, l3);
    size_t base = (size_t)i * 4;
    *(__half2*)&g_ah[base]     = __halves2half2(h0, h1);
    *(__half2*)&g_ah[base + 2] = __halves2half2(h2, h3);
    *(__half2*)&g_al[base]     = __halves2half2(l0, l1);
    *(__half2*)&g_al[base + 2] = __halves2half2(l2, l3);
}

// ================= mma.sync fp16 GEMM (GEMM0 / GEMM2) =================
template <int KTOT, int MODE, int TERMS>
__global__ void __launch_bounds__(256, 2) mma_gemm(
    const __half* __restrict__ Ah, const __half* __restrict__ Al,
    const __half* __restrict__ Bh,
    const float* __restrict__ bias,
    float* __restrict__ outf,
    __half* __restrict__ oh, int Nc,
    float* __restrict__ bnsum, float* __restrict__ bnsq)
{
    extern __shared__ __align__(16) char dynsm[];
    const uint32_t REG = 18432;
    const uint32_t BUFSTRIDE = (1 + TERMS) * REG;
    const uint32_t BOFF = TERMS * REG;
    uint32_t sbase = (uint32_t)__cvta_generic_to_shared(dynsm);
    __shared__ float ssum[128];
    __shared__ float ssq[128];

    int tid = threadIdx.x, lane = tid & 31, wid = tid >> 5;
    int wm = wid & 3, wn = wid >> 2;
    size_t row0 = (size_t)blockIdx.x * 128;
    int col0 = blockIdx.y * 128;

    if (MODE == 2 && tid < 128) { ssum[tid] = 0.f; ssq[tid] = 0.f; }

    const __half* Abh = Ah + row0 * KTOT;
    const __half* Abl = (TERMS == 2) ? (Al + row0 * KTOT) : nullptr;
    const __half* Bbh = Bh + (size_t)col0 * KTOT;

    float d[2][8][4];
#pragma unroll
    for (int i = 0; i < 2; i++)
#pragma unroll
        for (int j = 0; j < 8; j++)
#pragma unroll
            for (int k = 0; k < 4; k++) d[i][j][k] = 0.f;

    int a_row = wm * 32 + (lane & 7) + ((lane >> 3) & 1) * 8;
    int a_col = ((lane >> 4) & 1) * 8;
    uint32_t a_off = (uint32_t)(a_row * 72 + a_col) * 2;
    int b_row = wn * 64 + (lane & 7) + ((lane >> 4) & 1) * 8;
    int b_col = ((lane >> 3) & 1) * 8;
    uint32_t b_off = (uint32_t)(b_row * 72 + b_col) * 2;

    const int NCH = KTOT / 64;

#define ISSUE_CHUNK(CH, BUF) do { \
    int _kc = (CH); \
    uint32_t _s = sbase + (uint32_t)(BUF) * BUFSTRIDE; \
    _Pragma("unroll") \
    for (int _it = 0; _it < 4; _it++) { \
        int _idx = tid + _it * 256; \
        int _r = _idx >> 3, _c8 = _idx & 7; \
        uint32_t _soff = (uint32_t)(_r * 144 + _c8 * 16); \
        size_t _goff = (size_t)_r * KTOT + _kc * 64 + _c8 * 8; \
        CP_ASYNC16(_s + _soff, Abh + _goff); \
        if (TERMS == 2) CP_ASYNC16(_s + REG + _soff, Abl + _goff); \
        CP_ASYNC16(_s + BOFF + _soff, Bbh + _goff); \
    } \
    CP_COMMIT(); \
} while (0)

    ISSUE_CHUNK(0, 0);
    for (int ch = 0; ch < NCH; ch++) {
        if (ch + 1 < NCH) {
            ISSUE_CHUNK(ch + 1, (ch + 1) & 1);
            CP_WAIT1();
        } else {
            CP_WAIT0();
        }
        __syncthreads();
        uint32_t bufb = sbase + (uint32_t)(ch & 1) * BUFSTRIDE;
#pragma unroll
        for (int ks = 0; ks < 4; ks++) {
            uint32_t ah[2][4], al[2][4];
            uint32_t ad = bufb + a_off + (uint32_t)(ks * 32);
            LDSM4(ah[0][0], ah[0][1], ah[0][2], ah[0][3], ad);
            LDSM4(ah[1][0], ah[1][1], ah[1][2], ah[1][3], ad + 16 * 144);
            if (TERMS == 2) {
                uint32_t ald = ad + REG;
                LDSM4(al[0][0], al[0][1], al[0][2], al[0][3], ald);
                LDSM4(al[1][0], al[1][1], al[1][2], al[1][3], ald + 16 * 144);
            }
#pragma unroll
            for (int g = 0; g < 4; g++) {
                uint32_t b0, b1, b2, b3;
                uint32_t bd = bufb + BOFF + b_off + (uint32_t)(g * 16 * 144 + ks * 32);
                LDSM4(b0, b1, b2, b3, bd);
                MMA16816(d[0][2 * g],     ah[0], b0, b1);
                MMA16816(d[1][2 * g],     ah[1], b0, b1);
                MMA16816(d[0][2 * g + 1], ah[0], b2, b3);
                MMA16816(d[1][2 * g + 1], ah[1], b2, b3);
                if (TERMS == 2) {
                    MMA16816(d[0][2 * g],     al[0], b0, b1);
                    MMA16816(d[1][2 * g],     al[1], b0, b1);
                    MMA16816(d[0][2 * g + 1], al[0], b2, b3);
                    MMA16816(d[1][2 * g + 1], al[1], b2, b3);
                }
            }
        }
        __syncthreads();
    }
#undef ISSUE_CHUNK

    int r_base = (int)row0 + wm * 32 + (lane >> 2);
    int c_base = col0 + wn * 64 + 2 * (lane & 3);
#pragma unroll
    for (int mi = 0; mi < 2; mi++) {
#pragma unroll
        for (int ni = 0; ni < 8; ni++) {
            int gc = c_base + ni * 8;
            int r = r_base + mi * 16;
            if (MODE == 0) {
                float bz0 = __ldg(&bias[gc]);
                float bz1 = __ldg(&bias[gc + 1]);
                *(__half2*)&oh[(size_t)r * Nc + gc] =
                    __floats2half2_rn(d[mi][ni][0] + bz0, d[mi][ni][1] + bz1);
                *(__half2*)&oh[(size_t)(r + 8) * Nc + gc] =
                    __floats2half2_rn(d[mi][ni][2] + bz0, d[mi][ni][3] + bz1);
            } else {
                float2 o0, o1;
                o0.x = d[mi][ni][0]; o0.y = d[mi][ni][1];
                o1.x = d[mi][ni][2]; o1.y = d[mi][ni][3];
                *(float2*)&outf[(size_t)r * Nc + gc] = o0;
                *(float2*)&outf[(size_t)(r + 8) * Nc + gc] = o1;
            }
        }
    }

    if (MODE == 2) {
        float cs[8][2], cq[8][2];
#pragma unroll
        for (int ni = 0; ni < 8; ni++) { cs[ni][0] = cs[ni][1] = cq[ni][0] = cq[ni][1] = 0.f; }
#pragma unroll
        for (int mi = 0; mi < 2; mi++) {
            int rA = r_base + mi * 16;
            bool mA = rA < N_NODES, mB = (rA + 8) < N_NODES;
#pragma unroll
            for (int ni = 0; ni < 8; ni++) {
                float v0 = mA ? d[mi][ni][0] : 0.f;
                float v1 = mA ? d[mi][ni][1] : 0.f;
                float v2 = mB ? d[mi][ni][2] : 0.f;
                float v3 = mB ? d[mi][ni][3] : 0.f;
                cs[ni][0] += v0 + v2;  cs[ni][1] += v1 + v3;
                cq[ni][0] += v0 * v0 + v2 * v2;
                cq[ni][1] += v1 * v1 + v3 * v3;
            }
        }
#pragma unroll
        for (int off = 4; off <= 16; off <<= 1) {
#pragma unroll
            for (int ni = 0; ni < 8; ni++) {
                cs[ni][0] += __shfl_xor_sync(0xFFFFFFFF, cs[ni][0], off);
                cs[ni][1] += __shfl_xor_sync(0xFFFFFFFF, cs[ni][1], off);
                cq[ni][0] += __shfl_xor_sync(0xFFFFFFFF, cq[ni][0], off);
                cq[ni][1] += __shfl_xor_sync(0xFFFFFFFF, cq[ni][1], off);
            }
        }
        if ((lane >> 2) == 0) {
            int cb = wn * 64 + 2 * lane;
#pragma unroll
            for (int ni = 0; ni < 8; ni++) {
                atomicAdd(&ssum[cb + ni * 8],     cs[ni][0]);
                atomicAdd(&ssum[cb + ni * 8 + 1], cs[ni][1]);
                atomicAdd(&ssq[cb + ni * 8],      cq[ni][0]);
                atomicAdd(&ssq[cb + ni * 8 + 1],  cq[ni][1]);
            }
        }
        __syncthreads();
        if (tid < 128) {
            atomicAdd(&bnsum[tid], ssum[tid]);
            atomicAdd(&bnsq[tid],  ssq[tid]);
        }
    }
}

// ================= fused gather + GEMM1 =================
// One CTA per 128-node tile. Warps gather their 16 nodes each into the smem
// A-tile (72-padded fp16, 2 K-chunk regions) while W1 B-tiles prefetch via
// cp.async; then 4 GEMM steps (2 col-groups x 2 K-chunks) produce
// hidden = relu(A@W1+b1) -> g_hh fp16.
// Smem: [A0 | A1 | B0 | B1], 18432B each (dynamic), + 8KB static sWe.
__global__ void __launch_bounds__(256, 2) fused_g1(
    const float* __restrict__ We_l, const float* __restrict__ be_l,
    const __half* __restrict__ W1l, const float* __restrict__ b1l,
    __half* __restrict__ hh)
{
    extern __shared__ __align__(16) char dynsm[];
    const uint32_t REG = 18432;
    uint32_t sbase = (uint32_t)__cvta_generic_to_shared(dynsm);
    __shared__ float sWe[EDGE_F * EMB];

    int tid = threadIdx.x, lane = tid & 31, wid = tid >> 5;
    int wm = wid & 3, wn = wid >> 2;
    int row0 = blockIdx.x * 128;

    for (int i = tid; i < EDGE_F * EMB; i += 256) sWe[i] = We_l[i];

#define ISSUE_B(S, BUF) do { \
    int _cg = (S) >> 1, _kc = (S) & 1; \
    const __half* _bs = W1l + (size_t)_cg * 128 * 128 + _kc * 64; \
    uint32_t _sb = sbase + (uint32_t)(2 + (BUF)) * REG; \
    _Pragma("unroll") \
    for (int _it = 0; _it < 4; _it++) { \
        int _idx = tid + _it * 256; \
        int _r = _idx >> 3, _c8 = _idx & 7; \
        CP_ASYNC16(_sb + (uint32_t)(_r * 144 + _c8 * 16), \
                   _bs + (size_t)_r * 128 + _c8 * 8); \
    } \
    CP_COMMIT(); \
} while (0)

    // prefetch B steps 0,1 (arrive during the gather phase)
    ISSUE_B(0, 0);
    ISSUE_B(1, 1);
    __syncthreads();   // sWe visible

    // ---------------- gather phase: warp w -> nodes row0 + w*16 .. +15 ----------------
    {
        const float2* h2p = (const float2*)g_h;
        float4 bb = __ldg(&((const float4*)be_l)[lane]);
        uint32_t c0 = (uint32_t)lane * 4;
        char* abase = dynsm + (c0 >> 6) * REG + (c0 & 63) * 2;
        for (int i = 0; i < 16; i++) {
            int rl = wid * 16 + i;
            int node = row0 + rl;
            float4 acc = make_float4(0.f, 0.f, 0.f, 0.f);
            if (node < N_NODES) {
                int beg = g_rowptr[node], end = g_rowptr[node + 1];
                {
                    float2 raw = __ldg(&h2p[(size_t)node * 32 + lane]);  // self loop
                    ACC_ROW(acc, raw);
                }
                int e = beg;
                for (; e + 4 <= end; e += 4) {
                    float2 r0 = __ldg(&h2p[(size_t)g_csr_src[e]     * 32 + lane]);
                    float2 r1 = __ldg(&h2p[(size_t)g_csr_src[e + 1] * 32 + lane]);
                    float2 r2 = __ldg(&h2p[(size_t)g_csr_src[e + 2] * 32 + lane]);
                    float2 r3 = __ldg(&h2p[(size_t)g_csr_src[e + 3] * 32 + lane]);
                    ACC_ROW(acc, r0); ACC_ROW(acc, r1);
                    ACC_ROW(acc, r2); ACC_ROW(acc, r3);
                }
                for (; e < end; e++) {
                    float2 r0 = __ldg(&h2p[(size_t)g_csr_src[e] * 32 + lane]);
                    ACC_ROW(acc, r0);
                }
                int deg = end - beg;
#pragma unroll
                for (int k = 0; k < EDGE_F; k++) {
                    float s = g_S[node * EDGE_F + k];
                    float4 w = *(const float4*)&sWe[k * EMB + lane * 4];
                    acc.x += s * w.x; acc.y += s * w.y;
                    acc.z += s * w.z; acc.w += s * w.w;
                }
                float c = (float)(deg + 1);
                acc.x += c * bb.x; acc.y += c * bb.y;
                acc.z += c * bb.z; acc.w += c * bb.w;
            }
            char* ap = abase + (uint32_t)rl * 144;
            *(__half2*)ap       = __floats2half2_rn(acc.x, acc.y);
            *(__half2*)(ap + 4) = __floats2half2_rn(acc.z, acc.w);
        }
    }
    __syncthreads();   // A tile complete

    // ---------------- GEMM phase: 4 steps ----------------
    float d[2][8][4];
#pragma unroll
    for (int i = 0; i < 2; i++)
#pragma unroll
        for (int j = 0; j < 8; j++)
#pragma unroll
            for (int k = 0; k < 4; k++) d[i][j][k] = 0.f;

    int a_row = wm * 32 + (lane & 7) + ((lane >> 3) & 1) * 8;
    int a_col = ((lane >> 4) & 1) * 8;
    uint32_t a_off = (uint32_t)(a_row * 72 + a_col) * 2;
    int b_row = wn * 64 + (lane & 7) + ((lane >> 4) & 1) * 8;
    int b_col = ((lane >> 3) & 1) * 8;
    uint32_t b_off = (uint32_t)(b_row * 72 + b_col) * 2;

    int r_local = wm * 32 + (lane >> 2);
    int c_local = wn * 64 + 2 * (lane & 3);

    for (int s = 0; s < 4; s++) {
        if (s == 3) { CP_WAIT0(); } else { CP_WAIT1(); }
        __syncthreads();
        uint32_t abuf = sbase + (uint32_t)(s & 1) * REG;
        uint32_t bbuf = sbase + (uint32_t)(2 + (s & 1)) * REG;
#pragma unroll
        for (int ks = 0; ks < 4; ks++) {
            uint32_t a[2][4];
            uint32_t ad = abuf + a_off + (uint32_t)(ks * 32);
            LDSM4(a[0][0], a[0][1], a[0][2], a[0][3], ad);
            LDSM4(a[1][0], a[1][1], a[1][2], a[1][3], ad + 16 * 144);
#pragma unroll
            for (int g = 0; g < 4; g++) {
                uint32_t b0, b1, b2, b3;
                uint32_t bd = bbuf + b_off + (uint32_t)(g * 16 * 144 + ks * 32);
                LDSM4(b0, b1, b2, b3, bd);
                MMA16816(d[0][2 * g],     a[0], b0, b1);
                MMA16816(d[1][2 * g],     a[1], b0, b1);
                MMA16816(d[0][2 * g + 1], a[0], b2, b3);
                MMA16816(d[1][2 * g + 1], a[1], b2, b3);
            }
        }
        __syncthreads();
        if (s + 2 < 4) ISSUE_B(s + 2, s & 1);

        if (s & 1) {
            // col-group epilogue: relu(d + b1) -> g_hh; reset accumulators
            int cg = s >> 1;
#pragma unroll
            for (int mi = 0; mi < 2; mi++) {
#pragma unroll
                for (int ni = 0; ni < 8; ni++) {
                    int gc = c_local + ni * 8;
                    float bz0 = __ldg(&b1l[cg * 128 + gc]);
                    float bz1 = __ldg(&b1l[cg * 128 + gc + 1]);
                    int r = row0 + r_local + mi * 16;
                    *(__half2*)&hh[(size_t)r * HID + cg * 128 + gc] =
                        __floats2half2_rn(fmaxf(d[mi][ni][0] + bz0, 0.f),
                                          fmaxf(d[mi][ni][1] + bz1, 0.f));
                    *(__half2*)&hh[(size_t)(r + 8) * HID + cg * 128 + gc] =
                        __floats2half2_rn(fmaxf(d[mi][ni][2] + bz0, 0.f),
                                          fmaxf(d[mi][ni][3] + bz1, 0.f));
#pragma unroll
                    for (int k = 0; k < 4; k++) d[mi][ni][k] = 0.f;
                }
            }
        }
    }
#undef ISSUE_B
}

// ================= BatchNorm apply =================
template <int RELU, int HOUT>
__global__ void __launch_bounds__(256) k_bnapply(
    const float* __restrict__ H, void* __restrict__ O,
    const float* __restrict__ bnsum, const float* __restrict__ bnsq,
    const float* __restrict__ gamma_l, const float* __restrict__ beta_l)
{
    __shared__ float s_scale[EMB];
    __shared__ float s_shift[EMB];
    if (threadIdx.x < EMB) {
        int f = threadIdx.x;
        float inv_n = 1.f / (float)N_NODES;
        float mean = __ldg(&bnsum[f]) * inv_n;
        float var = __ldg(&bnsq[f]) * inv_n - mean * mean;
        float sc = __ldg(&gamma_l[f]) * rsqrtf(var + BN_EPS);
        s_scale[f] = sc;
        s_shift[f] = __ldg(&beta_l[f]) - mean * sc;
    }
    __syncthreads();
    int idx = blockIdx.x * blockDim.x + threadIdx.x;
    if (idx >= N_NODES * 32) return;
    int c4 = idx & 31;
    float4 v = ((const float4*)H)[idx];
    float4 sc = ((const float4*)s_scale)[c4];
    float4 sh = ((const float4*)s_shift)[c4];
    float4 o;
    o.x = v.x * sc.x + sh.x;
    o.y = v.y * sc.y + sh.y;
    o.z = v.z * sc.z + sh.z;
    o.w = v.w * sc.w + sh.w;
    if (RELU) {
        o.x = fmaxf(o.x, 0.f); o.y = fmaxf(o.y, 0.f);
        o.z = fmaxf(o.z, 0.f); o.w = fmaxf(o.w, 0.f);
    }
    if (HOUT) {
        __half* O16 = (__half*)O;
        *(__half2*)&O16[(size_t)idx * 4]     = __floats2half2_rn(o.x, o.y);
        *(__half2*)&O16[(size_t)idx * 4 + 2] = __floats2half2_rn(o.z, o.w);
    } else {
        ((float4*)O)[idx] = o;
    }
}

// ================= launch =================
extern "C" void kernel_launch(void* const* d_in, const int* in_sizes, int n_in,
                              void* d_out, int out_size) {
    const float* x         = (const float*)d_in[0];
    const float* edge_attr = (const float*)d_in[1];
    const int*   ei        = (const int*)d_in[2];
    const float* Wx        = (const float*)d_in[3];
    const float* bx        = (const float*)d_in[4];
    const float* We        = (const float*)d_in[5];
    const float* be        = (const float*)d_in[6];
    const float* W1        = (const float*)d_in[7];
    const float* b1        = (const float*)d_in[8];
    const float* W2        = (const float*)d_in[9];
    const float* b2        = (const float*)d_in[10];  // unused: cancels in BN
    const float* gamma     = (const float*)d_in[11];
    const float* beta      = (const float*)d_in[12];
    float* out = (float*)d_out;
    (void)b2;

    float *p_agg, *p_bsum, *p_bsq;
    __half *p_ah, *p_al, *p_hh, *p_h, *p_wxh, *p_w1h, *p_w2h;
    cudaGetSymbolAddress((void**)&p_h,    g_h);
    cudaGetSymbolAddress((void**)&p_agg,  g_agg);
    cudaGetSymbolAddress((void**)&p_bsum, g_bsum);
    cudaGetSymbolAddress((void**)&p_bsq,  g_bsq);
    cudaGetSymbolAddress((void**)&p_ah,   g_ah);
    cudaGetSymbolAddress((void**)&p_al,   g_al);
    cudaGetSymbolAddress((void**)&p_hh,   g_hh);
    cudaGetSymbolAddress((void**)&p_wxh,  g_wxh);
    cudaGetSymbolAddress((void**)&p_w1h,  g_w1h);
    cudaGetSymbolAddress((void**)&p_w2h,  g_w2h);

    const int DYNSM2 = 2 * 3 * 18432;  // 110592 (GEMM0: 2 stages x (Ah|Al|B))
    const int DYNSM1 = 2 * 2 * 18432;  // 73728  (GEMM2: 2 stages x (Ah|B))
    const int DYNSMF = 4 * 18432;      // 73728  (fused: A0|A1|B0|B1)
    cudaFuncSetAttribute(mma_gemm<128, 0, 2>, cudaFuncAttributeMaxDynamicSharedMemorySize, DYNSM2);
    cudaFuncSetAttribute(mma_gemm<256, 2, 1>, cudaFuncAttributeMaxDynamicSharedMemorySize, DYNSM1);
    cudaFuncSetAttribute(fused_g1, cudaFuncAttributeMaxDynamicSharedMemorySize, DYNSMF);

    const int NTILES = NP / 128;  // 391
    const int PREPN = NLAYERS * EMB * HID;

    // Launch order: #4 = mma_gemm (GEMM0) for the ncu capture slot.
    k_prep<<<(PREPN + 255) / 256, 256>>>(Wx, W1, W2);                           // 1
    k_xsplit<<<(N_NODES * EMB / 4 + 255) / 256, 256>>>(x);                      // 2
    k_hist<<<(N_EDGES + 255) / 256, 256>>>(ei);                                 // 3
    mma_gemm<128, 0, 2><<<dim3(NTILES, 1), 256, DYNSM2>>>(p_ah, p_al, p_wxh,    // 4
        bx, nullptr, p_h, 128, nullptr, nullptr);
    k_scan<<<1, 1024>>>();                                                      // 5
    k_fill<<<(N_EDGES + 255) / 256, 256>>>(ei);                                 // 6
    k_ssum<<<(N_NODES * 32 + 255) / 256, 256>>>(edge_attr);                     // 7

    for (int l = 0; l < NLAYERS; l++) {
        fused_g1<<<NTILES, 256, DYNSMF>>>(
            We + (size_t)l * EDGE_F * EMB, be + (size_t)l * EMB,
            p_w1h + (size_t)l * HID * EMB, b1 + (size_t)l * HID, p_hh);
        mma_gemm<256, 2, 1><<<dim3(NTILES, 1), 256, DYNSM1>>>(
            p_hh, nullptr, p_w2h + (size_t)l * EMB * HID,
            nullptr, p_agg, nullptr, 128,
            p_bsum + l * EMB, p_bsq + l * EMB);
        if (l < NLAYERS - 1)
            k_bnapply<1, 1><<<(N_NODES * 32 + 255) / 256, 256>>>(
                p_agg, (void*)p_h, p_bsum + l * EMB, p_bsq + l * EMB,
                gamma + (size_t)l * EMB, beta + (size_t)l * EMB);
        else
            k_bnapply<0, 0><<<(N_NODES * 32 + 255) / 256, 256>>>(
                p_agg, (void*)out, p_bsum + l * EMB, p_bsq + l * EMB,
                gamma + (size_t)l * EMB, beta + (size_t)l * EMB);
    }
}

// round 15
// speedup vs baseline: 1.4027x; 1.4027x over previous
#include <cuda_runtime.h>
#include <cuda_fp16.h>
#include <cstdint>

#define N_NODES 50000
#define NP      50048            // padded to 391*128
#define N_EDGES 800000
#define EMB     128
#define HID     256
#define EDGE_F  16
#define NLAYERS 5
#define BN_EPS  1e-5f
#define NTILES  391
#define GRID2   296              // 2 CTAs/SM * 148 SMs (persistent GEMM2)

// ================= device scratch (static, no allocation) =================
__device__ __half g_ah[NP * EMB];   // x-split hi (GEMM0 A) / gather out (GEMM1 A)
__device__ __half g_al[NP * EMB];   // x-split lo (GEMM0 A residual)
__device__ __half g_hh[NP * HID];   // hidden (GEMM2 A, single fp16 term)
__device__ __half g_h[NP * EMB];    // node features (fp16)
__device__ float g_agg[NP * EMB];   // layer out (pre-BN, fp32)
__device__ __half g_wxh[EMB * EMB];            // weights: fp16, [N][K] transposed
__device__ __half g_w1h[NLAYERS * HID * EMB];
__device__ __half g_w2h[NLAYERS * EMB * HID];
__device__ float g_S[N_NODES * EDGE_F];
__device__ int   g_deg[N_NODES];
__device__ int   g_fill[N_NODES];
__device__ int   g_rowptr[N_NODES + 1];
__device__ int   g_csr_src[N_EDGES];
__device__ int   g_csr_eid[N_EDGES];
__device__ float g_bsum[NLAYERS * EMB];
__device__ float g_bsq[NLAYERS * EMB];
__device__ int   g_sync[NLAYERS];          // per-layer grid-barrier counters

__device__ __forceinline__ void split_f16(float v, __half& hi, __half& lo) {
    hi = __float2half_rn(v);
    lo = __float2half_rn(v - __half2float(hi));
}

#define LDSM4(r0, r1, r2, r3, addr) \
    asm volatile("ldmatrix.sync.aligned.m8n8.x4.shared.b16 {%0,%1,%2,%3}, [%4];" \
                 : "=r"(r0), "=r"(r1), "=r"(r2), "=r"(r3) : "r"(addr))

#define MMA16816(d, a, b0, b1) \
    asm volatile("mma.sync.aligned.m16n8k16.row.col.f32.f16.f16.f32 " \
                 "{%0,%1,%2,%3},{%4,%5,%6,%7},{%8,%9},{%0,%1,%2,%3};" \
                 : "+f"((d)[0]), "+f"((d)[1]), "+f"((d)[2]), "+f"((d)[3]) \
                 : "r"((a)[0]), "r"((a)[1]), "r"((a)[2]), "r"((a)[3]), \
                   "r"(b0), "r"(b1))

#define CP_ASYNC16(dst, src) \
    asm volatile("cp.async.cg.shared.global [%0], [%1], 16;" :: "r"(dst), "l"(src))
#define CP_COMMIT() asm volatile("cp.async.commit_group;")
#define CP_WAIT1()  asm volatile("cp.async.wait_group 1;")
#define CP_WAIT0()  asm volatile("cp.async.wait_group 0;")

#define ACC_ROW(acc, raw) do { \
    const __half2* _p = (const __half2*)&(raw); \
    float2 _a = __half22float2(_p[0]); \
    float2 _b = __half22float2(_p[1]); \
    (acc).x += _a.x; (acc).y += _a.y; (acc).z += _b.x; (acc).w += _b.y; \
} while (0)

// ================= combined prep =================
__global__ void k_prep(const float* __restrict__ Wx, const float* __restrict__ W1,
                       const float* __restrict__ W2) {
    int i = blockIdx.x * blockDim.x + threadIdx.x;
    if (i < N_NODES) { g_deg[i] = 0; g_fill[i] = 0; }
    if (i < NLAYERS * EMB) { g_bsum[i] = 0.f; g_bsq[i] = 0.f; }
    if (i < NLAYERS) g_sync[i] = 0;
    if (i < EMB * EMB) {
        int k = i / EMB, n = i - k * EMB;
        g_wxh[n * EMB + k] = __float2half_rn(Wx[i]);
    }
    if (i < NLAYERS * EMB * HID) {
        int l = i / (EMB * HID);
        int r = i - l * (EMB * HID);
        int k = r / HID, n = r - k * HID;
        g_w1h[l * EMB * HID + n * EMB + k] = __float2half_rn(W1[i]);
    }
    if (i < NLAYERS * HID * EMB) {
        int l = i / (HID * EMB);
        int r = i - l * (HID * EMB);
        int k = r / EMB, n = r - k * EMB;
        g_w2h[l * HID * EMB + n * HID + k] = __float2half_rn(W2[i]);
    }
}

__global__ void k_hist(const int* __restrict__ ei) {
    int e = blockIdx.x * blockDim.x + threadIdx.x;
    if (e < N_EDGES) atomicAdd(&g_deg[ei[N_EDGES + e]], 1);
}
__global__ void k_scan() {
    const int NT = 1024;
    const int CH = (N_NODES + NT - 1) / NT;
    __shared__ int sh[NT];
    int t = threadIdx.x;
    int s0 = t * CH, s1 = s0 + CH;
    if (s1 > N_NODES) s1 = N_NODES;
    int s = 0;
    for (int i = s0; i < s1; i++) s += g_deg[i];
    sh[t] = s;
    __syncthreads();
    for (int off = 1; off < NT; off <<= 1) {
        int v = (t >= off) ? sh[t - off] : 0;
        __syncthreads();
        sh[t] += v;
        __syncthreads();
    }
    int run = sh[t] - s;
    for (int i = s0; i < s1; i++) { g_rowptr[i] = run; run += g_deg[i]; }
    if (t == NT - 1) g_rowptr[N_NODES] = sh[NT - 1];
}
__global__ void k_fill(const int* __restrict__ ei) {
    int e = blockIdx.x * blockDim.x + threadIdx.x;
    if (e >= N_EDGES) return;
    int src = ei[e];
    int dst = ei[N_EDGES + e];
    int pos = g_rowptr[dst] + atomicAdd(&g_fill[dst], 1);
    g_csr_src[pos] = src;
    g_csr_eid[pos] = e;
}
__global__ void k_ssum(const float* __restrict__ ea) {
    int gw = (blockIdx.x * blockDim.x + threadIdx.x) >> 5;
    int lane = threadIdx.x & 31;
    if (gw >= N_NODES || lane >= EDGE_F) return;
    int beg = g_rowptr[gw], end = g_rowptr[gw + 1];
    float s = 0.f;
    for (int e = beg; e < end; e++)
        s += ea[(size_t)g_csr_eid[e] * EDGE_F + lane];
    g_S[gw * EDGE_F + lane] = s;
}

// x -> fp16 hi/lo split (float4 vectorized)
__global__ void k_xsplit(const float* __restrict__ x) {
    int i = blockIdx.x * blockDim.x + threadIdx.x;
    if (i >= N_NODES * EMB / 4) return;
    float4 v = __ldg(&((const float4*)x)[i]);
    __half h0, l0, h1, l1, h2, l2, h3, l3;
    split_f16(v.x, h0, l0); split_f16(v.y, h1, l1);
    split_f16(v.z, h2, l2); split_f16(v.w, h3, l3);
    size_t base = (size_t)i * 4;
    *(__half2*)&g_ah[base]     = __halves2half2(h0, h1);
    *(__half2*)&g_ah[base + 2] = __halves2half2(h2, h3);
    *(__half2*)&g_al[base]     = __halves2half2(l0, l1);
    *(__half2*)&g_al[base + 2] = __halves2half2(l2, l3);
}

// ================= gather / aggregate (warp per node, wide grid) =================
__global__ void __launch_bounds__(256) k_gather(const float* __restrict__ We_l,
                                                const float* __restrict__ be_l) {
    __shared__ float sWe[EDGE_F * EMB];
    for (int i = threadIdx.x; i < EDGE_F * EMB; i += blockDim.x) sWe[i] = We_l[i];
    __syncthreads();

    int gw = (blockIdx.x * blockDim.x + threadIdx.x) >> 5;
    int lane = threadIdx.x & 31;
    if (gw >= N_NODES) return;

    const float2* h2p = (const float2*)g_h;
    int beg = g_rowptr[gw], end = g_rowptr[gw + 1];

    float4 acc = make_float4(0.f, 0.f, 0.f, 0.f);
    {
        float2 raw = __ldg(&h2p[(size_t)gw * 32 + lane]);   // self loop
        ACC_ROW(acc, raw);
    }
    int e = beg;
    for (; e + 2 <= end; e += 2) {
        float2 r0 = __ldg(&h2p[(size_t)g_csr_src[e] * 32 + lane]);
        float2 r1 = __ldg(&h2p[(size_t)g_csr_src[e + 1] * 32 + lane]);
        ACC_ROW(acc, r0);
        ACC_ROW(acc, r1);
    }
    if (e < end) {
        float2 r0 = __ldg(&h2p[(size_t)g_csr_src[e] * 32 + lane]);
        ACC_ROW(acc, r0);
    }

    int deg = end - beg;
#pragma unroll
    for (int k = 0; k < EDGE_F; k++) {
        float s = g_S[gw * EDGE_F + k];
        float4 w = *(const float4*)&sWe[k * EMB + lane * 4];
        acc.x += s * w.x; acc.y += s * w.y;
        acc.z += s * w.z; acc.w += s * w.w;
    }
    float c = (float)(deg + 1);
    float4 bb = __ldg(&((const float4*)be_l)[lane]);
    acc.x += c * bb.x; acc.y += c * bb.y;
    acc.z += c * bb.z; acc.w += c * bb.w;

    size_t base = (size_t)gw * EMB + lane * 4;
    *(__half2*)&g_ah[base]     = __floats2half2_rn(acc.x, acc.y);
    *(__half2*)&g_ah[base + 2] = __floats2half2_rn(acc.z, acc.w);
}

// ================= mma.sync fp16 GEMM (GEMM0 / GEMM1) =================
// TERMS=2: C = (Ah + Al) @ Bh.  TERMS=1: C = Ah @ Bh.
// MODE 0: oh = fp16(C + bias).  MODE 1: oh = fp16(relu(C + bias)).
template <int KTOT, int MODE, int TERMS>
__global__ void __launch_bounds__(256, 2) mma_gemm(
    const __half* __restrict__ Ah, const __half* __restrict__ Al,
    const __half* __restrict__ Bh,
    const float* __restrict__ bias,
    __half* __restrict__ oh, int Nc)
{
    extern __shared__ __align__(16) char dynsm[];
    const uint32_t REG = 18432;
    const uint32_t BUFSTRIDE = (1 + TERMS) * REG;
    const uint32_t BOFF = TERMS * REG;
    uint32_t sbase = (uint32_t)__cvta_generic_to_shared(dynsm);

    int tid = threadIdx.x, lane = tid & 31, wid = tid >> 5;
    int wm = wid & 3, wn = wid >> 2;
    size_t row0 = (size_t)blockIdx.x * 128;
    int col0 = blockIdx.y * 128;

    const __half* Abh = Ah + row0 * KTOT;
    const __half* Abl = (TERMS == 2) ? (Al + row0 * KTOT) : nullptr;
    const __half* Bbh = Bh + (size_t)col0 * KTOT;

    float d[2][8][4];
#pragma unroll
    for (int i = 0; i < 2; i++)
#pragma unroll
        for (int j = 0; j < 8; j++)
#pragma unroll
            for (int k = 0; k < 4; k++) d[i][j][k] = 0.f;

    int a_row = wm * 32 + (lane & 7) + ((lane >> 3) & 1) * 8;
    int a_col = ((lane >> 4) & 1) * 8;
    uint32_t a_off = (uint32_t)(a_row * 72 + a_col) * 2;
    int b_row = wn * 64 + (lane & 7) + ((lane >> 4) & 1) * 8;
    int b_col = ((lane >> 3) & 1) * 8;
    uint32_t b_off = (uint32_t)(b_row * 72 + b_col) * 2;

    const int NCH = KTOT / 64;

#define ISSUE_CHUNK(CH, BUF) do { \
    int _kc = (CH); \
    uint32_t _s = sbase + (uint32_t)(BUF) * BUFSTRIDE; \
    _Pragma("unroll") \
    for (int _it = 0; _it < 4; _it++) { \
        int _idx = tid + _it * 256; \
        int _r = _idx >> 3, _c8 = _idx & 7; \
        uint32_t _soff = (uint32_t)(_r * 144 + _c8 * 16); \
        size_t _goff = (size_t)_r * KTOT + _kc * 64 + _c8 * 8; \
        CP_ASYNC16(_s + _soff, Abh + _goff); \
        if (TERMS == 2) CP_ASYNC16(_s + REG + _soff, Abl + _goff); \
        CP_ASYNC16(_s + BOFF + _soff, Bbh + _goff); \
    } \
    CP_COMMIT(); \
} while (0)

    ISSUE_CHUNK(0, 0);
    for (int ch = 0; ch < NCH; ch++) {
        if (ch + 1 < NCH) {
            ISSUE_CHUNK(ch + 1, (ch + 1) & 1);
            CP_WAIT1();
        } else {
            CP_WAIT0();
        }
        __syncthreads();
        uint32_t bufb = sbase + (uint32_t)(ch & 1) * BUFSTRIDE;
#pragma unroll
        for (int ks = 0; ks < 4; ks++) {
            uint32_t ah[2][4], al[2][4];
            uint32_t ad = bufb + a_off + (uint32_t)(ks * 32);
            LDSM4(ah[0][0], ah[0][1], ah[0][2], ah[0][3], ad);
            LDSM4(ah[1][0], ah[1][1], ah[1][2], ah[1][3], ad + 16 * 144);
            if (TERMS == 2) {
                uint32_t ald = ad + REG;
                LDSM4(al[0][0], al[0][1], al[0][2], al[0][3], ald);
                LDSM4(al[1][0], al[1][1], al[1][2], al[1][3], ald + 16 * 144);
            }
#pragma unroll
            for (int g = 0; g < 4; g++) {
                uint32_t b0, b1, b2, b3;
                uint32_t bd = bufb + BOFF + b_off + (uint32_t)(g * 16 * 144 + ks * 32);
                LDSM4(b0, b1, b2, b3, bd);
                MMA16816(d[0][2 * g],     ah[0], b0, b1);
                MMA16816(d[1][2 * g],     ah[1], b0, b1);
                MMA16816(d[0][2 * g + 1], ah[0], b2, b3);
                MMA16816(d[1][2 * g + 1], ah[1], b2, b3);
                if (TERMS == 2) {
                    MMA16816(d[0][2 * g],     al[0], b0, b1);
                    MMA16816(d[1][2 * g],     al[1], b0, b1);
                    MMA16816(d[0][2 * g + 1], al[0], b2, b3);
                    MMA16816(d[1][2 * g + 1], al[1], b2, b3);
                }
            }
        }
        __syncthreads();
    }
#undef ISSUE_CHUNK

    int r_base = (int)row0 + wm * 32 + (lane >> 2);
    int c_base = col0 + wn * 64 + 2 * (lane & 3);
#pragma unroll
    for (int mi = 0; mi < 2; mi++) {
#pragma unroll
        for (int ni = 0; ni < 8; ni++) {
            int gc = c_base + ni * 8;
            int r = r_base + mi * 16;
            float bz0 = __ldg(&bias[gc]);
            float bz1 = __ldg(&bias[gc + 1]);
            if (MODE == 0) {
                *(__half2*)&oh[(size_t)r * Nc + gc] =
                    __floats2half2_rn(d[mi][ni][0] + bz0, d[mi][ni][1] + bz1);
                *(__half2*)&oh[(size_t)(r + 8) * Nc + gc] =
                    __floats2half2_rn(d[mi][ni][2] + bz0, d[mi][ni][3] + bz1);
            } else {
                *(__half2*)&oh[(size_t)r * Nc + gc] =
                    __floats2half2_rn(fmaxf(d[mi][ni][0] + bz0, 0.f),
                                      fmaxf(d[mi][ni][1] + bz1, 0.f));
                *(__half2*)&oh[(size_t)(r + 8) * Nc + gc] =
                    __floats2half2_rn(fmaxf(d[mi][ni][2] + bz0, 0.f),
                                      fmaxf(d[mi][ni][3] + bz1, 0.f));
            }
        }
    }
}

// ================= persistent GEMM2 + grid barrier + fused BN apply =================
// Grid = GRID2 = 296 CTAs (exactly 2/SM -> co-resident). Each CTA processes tiles
// {bid, bid+296}. Phase 1: out = hidden @ W2 (fp32 agg) + BN stats. Barrier on an
// atomic counter. Phase 2: every CTA derives scale/shift and applies BN (+relu) to
// its own tiles: LAST=0 -> fp16 g_h; LAST=1 -> fp32 final out.
template <int LAST>
__global__ void __launch_bounds__(256, 2) gemm2_bn(
    const __half* __restrict__ Ah, const __half* __restrict__ Bh,
    float* __restrict__ agg, void* __restrict__ outp,
    float* __restrict__ bnsum, float* __restrict__ bnsq,
    const float* __restrict__ gamma_l, const float* __restrict__ beta_l,
    int* __restrict__ sync)
{
    extern __shared__ __align__(16) char dynsm[];
    const uint32_t REG = 18432;
    const uint32_t BUFSTRIDE = 2 * REG;       // A | B per stage
    uint32_t sbase = (uint32_t)__cvta_generic_to_shared(dynsm);
    __shared__ float ssum[128];
    __shared__ float ssq[128];

    int tid = threadIdx.x, lane = tid & 31, wid = tid >> 5;
    int wm = wid & 3, wn = wid >> 2;
    if (tid < 128) { ssum[tid] = 0.f; ssq[tid] = 0.f; }
    __syncthreads();

    int a_row = wm * 32 + (lane & 7) + ((lane >> 3) & 1) * 8;
    int a_col = ((lane >> 4) & 1) * 8;
    uint32_t a_off = (uint32_t)(a_row * 72 + a_col) * 2;
    int b_row = wn * 64 + (lane & 7) + ((lane >> 4) & 1) * 8;
    int b_col = ((lane >> 3) & 1) * 8;
    uint32_t b_off = (uint32_t)(b_row * 72 + b_col) * 2;

    for (int t = blockIdx.x; t < NTILES; t += GRID2) {
        const __half* Abh = Ah + (size_t)t * 128 * HID;

        float d[2][8][4];
#pragma unroll
        for (int i = 0; i < 2; i++)
#pragma unroll
            for (int j = 0; j < 8; j++)
#pragma unroll
                for (int k = 0; k < 4; k++) d[i][j][k] = 0.f;

#define ISSUE2(CH, BUF) do { \
    int _kc = (CH); \
    uint32_t _s = sbase + (uint32_t)(BUF) * BUFSTRIDE; \
    _Pragma("unroll") \
    for (int _it = 0; _it < 4; _it++) { \
        int _idx = tid + _it * 256; \
        int _r = _idx >> 3, _c8 = _idx & 7; \
        uint32_t _soff = (uint32_t)(_r * 144 + _c8 * 16); \
        size_t _goff = (size_t)_r * HID + _kc * 64 + _c8 * 8; \
        CP_ASYNC16(_s + _soff,       Abh + _goff); \
        CP_ASYNC16(_s + REG + _soff, Bh + _goff); \
    } \
    CP_COMMIT(); \
} while (0)

        ISSUE2(0, 0);
        for (int ch = 0; ch < 4; ch++) {
            if (ch + 1 < 4) { ISSUE2(ch + 1, (ch + 1) & 1); CP_WAIT1(); }
            else            { CP_WAIT0(); }
            __syncthreads();
            uint32_t bufb = sbase + (uint32_t)(ch & 1) * BUFSTRIDE;
#pragma unroll
            for (int ks = 0; ks < 4; ks++) {
                uint32_t a[2][4];
                uint32_t ad = bufb + a_off + (uint32_t)(ks * 32);
                LDSM4(a[0][0], a[0][1], a[0][2], a[0][3], ad);
                LDSM4(a[1][0], a[1][1], a[1][2], a[1][3], ad + 16 * 144);
#pragma unroll
                for (int g = 0; g < 4; g++) {
                    uint32_t b0, b1, b2, b3;
                    uint32_t bd = bufb + REG + b_off + (uint32_t)(g * 16 * 144 + ks * 32);
                    LDSM4(b0, b1, b2, b3, bd);
                    MMA16816(d[0][2 * g],     a[0], b0, b1);
                    MMA16816(d[1][2 * g],     a[1], b0, b1);
                    MMA16816(d[0][2 * g + 1], a[0], b2, b3);
                    MMA16816(d[1][2 * g + 1], a[1], b2, b3);
                }
            }
            __syncthreads();
        }
#undef ISSUE2

        // epilogue: write agg fp32 + accumulate BN stats into smem
        int r_base = t * 128 + wm * 32 + (lane >> 2);
        int c_base = wn * 64 + 2 * (lane & 3);
#pragma unroll
        for (int mi = 0; mi < 2; mi++) {
#pragma unroll
            for (int ni = 0; ni < 8; ni++) {
                int gc = c_base + ni * 8;
                int r = r_base + mi * 16;
                float2 o0, o1;
                o0.x = d[mi][ni][0]; o0.y = d[mi][ni][1];
                o1.x = d[mi][ni][2]; o1.y = d[mi][ni][3];
                *(float2*)&agg[(size_t)r * EMB + gc] = o0;
                *(float2*)&agg[(size_t)(r + 8) * EMB + gc] = o1;
            }
        }
        float cs[8][2], cq[8][2];
#pragma unroll
        for (int ni = 0; ni < 8; ni++) { cs[ni][0] = cs[ni][1] = cq[ni][0] = cq[ni][1] = 0.f; }
#pragma unroll
        for (int mi = 0; mi < 2; mi++) {
            int rA = r_base + mi * 16;
            bool mA = rA < N_NODES, mB = (rA + 8) < N_NODES;
#pragma unroll
            for (int ni = 0; ni < 8; ni++) {
                float v0 = mA ? d[mi][ni][0] : 0.f;
                float v1 = mA ? d[mi][ni][1] : 0.f;
                float v2 = mB ? d[mi][ni][2] : 0.f;
                float v3 = mB ? d[mi][ni][3] : 0.f;
                cs[ni][0] += v0 + v2;  cs[ni][1] += v1 + v3;
                cq[ni][0] += v0 * v0 + v2 * v2;
                cq[ni][1] += v1 * v1 + v3 * v3;
            }
        }
#pragma unroll
        for (int off = 4; off <= 16; off <<= 1) {
#pragma unroll
            for (int ni = 0; ni < 8; ni++) {
                cs[ni][0] += __shfl_xor_sync(0xFFFFFFFF, cs[ni][0], off);
                cs[ni][1] += __shfl_xor_sync(0xFFFFFFFF, cs[ni][1], off);
                cq[ni][0] += __shfl_xor_sync(0xFFFFFFFF, cq[ni][0], off);
                cq[ni][1] += __shfl_xor_sync(0xFFFFFFFF, cq[ni][1], off);
            }
        }
        if ((lane >> 2) == 0) {
            int cb = wn * 64 + 2 * lane;
#pragma unroll
            for (int ni = 0; ni < 8; ni++) {
                atomicAdd(&ssum[cb + ni * 8],     cs[ni][0]);
                atomicAdd(&ssum[cb + ni * 8 + 1], cs[ni][1]);
                atomicAdd(&ssq[cb + ni * 8],      cq[ni][0]);
                atomicAdd(&ssq[cb + ni * 8 + 1],  cq[ni][1]);
            }
        }
        __syncthreads();
    }

    // flush stats to global
    if (tid < 128) {
        atomicAdd(&bnsum[tid], ssum[tid]);
        atomicAdd(&bnsq[tid],  ssq[tid]);
    }
    __threadfence();
    __syncthreads();

    // ---- grid barrier (all GRID2 CTAs co-resident by construction) ----
    if (tid == 0) {
        atomicAdd(sync, 1);
        while (atomicAdd(sync, 0) < GRID2) { }
    }
    __syncthreads();

    // derive scale/shift (reuse ssum/ssq smem)
    if (tid < 128) {
        int f = tid;
        float inv_n = 1.f / (float)N_NODES;
        float mean = __ldcg(&bnsum[f]) * inv_n;
        float var = __ldcg(&bnsq[f]) * inv_n - mean * mean;
        float sc = __ldg(&gamma_l[f]) * rsqrtf(var + BN_EPS);
        ssum[f] = sc;
        ssq[f] = __ldg(&beta_l[f]) - mean * sc;
    }
    __syncthreads();

    // apply BN to own tiles
    for (int t = blockIdx.x; t < NTILES; t += GRID2) {
        for (int i = tid; i < 128 * 32; i += 256) {
            int row = t * 128 + (i >> 5);
            if (row >= N_NODES) continue;
            int c4 = i & 31;
            float4 v = *(const float4*)&agg[(size_t)row * EMB + c4 * 4];
            float4 sc = ((const float4*)ssum)[c4];
            float4 sh = ((const float4*)ssq)[c4];
            float4 o;
            o.x = v.x * sc.x + sh.x;
            o.y = v.y * sc.y + sh.y;
            o.z = v.z * sc.z + sh.z;
            o.w = v.w * sc.w + sh.w;
            if (!LAST) {
                o.x = fmaxf(o.x, 0.f); o.y = fmaxf(o.y, 0.f);
                o.z = fmaxf(o.z, 0.f); o.w = fmaxf(o.w, 0.f);
                __half* O16 = (__half*)outp;
                *(__half2*)&O16[(size_t)row * EMB + c4 * 4]     = __floats2half2_rn(o.x, o.y);
                *(__half2*)&O16[(size_t)row * EMB + c4 * 4 + 2] = __floats2half2_rn(o.z, o.w);
            } else {
                ((float4*)outp)[(size_t)row * 32 + c4] = o;
            }
        }
    }
}

// ================= launch =================
extern "C" void kernel_launch(void* const* d_in, const int* in_sizes, int n_in,
                              void* d_out, int out_size) {
    const float* x         = (const float*)d_in[0];
    const float* edge_attr = (const float*)d_in[1];
    const int*   ei        = (const int*)d_in[2];
    const float* Wx        = (const float*)d_in[3];
    const float* bx        = (const float*)d_in[4];
    const float* We        = (const float*)d_in[5];
    const float* be        = (const float*)d_in[6];
    const float* W1        = (const float*)d_in[7];
    const float* b1        = (const float*)d_in[8];
    const float* W2        = (const float*)d_in[9];
    const float* b2        = (const float*)d_in[10];  // unused: cancels in BN
    const float* gamma     = (const float*)d_in[11];
    const float* beta      = (const float*)d_in[12];
    float* out = (float*)d_out;
    (void)b2;

    float *p_agg, *p_bsum, *p_bsq;
    int* p_sync;
    __half *p_ah, *p_al, *p_hh, *p_h, *p_wxh, *p_w1h, *p_w2h;
    cudaGetSymbolAddress((void**)&p_h,    g_h);
    cudaGetSymbolAddress((void**)&p_agg,  g_agg);
    cudaGetSymbolAddress((void**)&p_bsum, g_bsum);
    cudaGetSymbolAddress((void**)&p_bsq,  g_bsq);
    cudaGetSymbolAddress((void**)&p_sync, g_sync);
    cudaGetSymbolAddress((void**)&p_ah,   g_ah);
    cudaGetSymbolAddress((void**)&p_al,   g_al);
    cudaGetSymbolAddress((void**)&p_hh,   g_hh);
    cudaGetSymbolAddress((void**)&p_wxh,  g_wxh);
    cudaGetSymbolAddress((void**)&p_w1h,  g_w1h);
    cudaGetSymbolAddress((void**)&p_w2h,  g_w2h);

    const int DYNSM2 = 2 * 3 * 18432;  // 110592 (GEMM0: 2 stages x (Ah|Al|B))
    const int DYNSM1 = 2 * 2 * 18432;  // 73728  (GEMM1/GEMM2: 2 stages x (A|B))
    cudaFuncSetAttribute(mma_gemm<128, 0, 2>, cudaFuncAttributeMaxDynamicSharedMemorySize, DYNSM2);
    cudaFuncSetAttribute(mma_gemm<128, 1, 1>, cudaFuncAttributeMaxDynamicSharedMemorySize, DYNSM1);
    cudaFuncSetAttribute(gemm2_bn<0>, cudaFuncAttributeMaxDynamicSharedMemorySize, DYNSM1);
    cudaFuncSetAttribute(gemm2_bn<1>, cudaFuncAttributeMaxDynamicSharedMemorySize, DYNSM1);

    const int PREPN = NLAYERS * EMB * HID;

    // Launch order: #4 = mma_gemm (GEMM0) for the ncu capture slot.
    k_prep<<<(PREPN + 255) / 256, 256>>>(Wx, W1, W2);                           // 1
    k_xsplit<<<(N_NODES * EMB / 4 + 255) / 256, 256>>>(x);                      // 2
    k_hist<<<(N_EDGES + 255) / 256, 256>>>(ei);                                 // 3
    mma_gemm<128, 0, 2><<<dim3(NTILES, 1), 256, DYNSM2>>>(p_ah, p_al, p_wxh,    // 4
        bx, p_h, 128);
    k_scan<<<1, 1024>>>();                                                      // 5
    k_fill<<<(N_EDGES + 255) / 256, 256>>>(ei);                                 // 6
    k_ssum<<<(N_NODES * 32 + 255) / 256, 256>>>(edge_attr);                     // 7

    for (int l = 0; l < NLAYERS; l++) {
        k_gather<<<(N_NODES * 32 + 255) / 256, 256>>>(We + (size_t)l * EDGE_F * EMB,
                                                      be + (size_t)l * EMB);
        mma_gemm<128, 1, 1><<<dim3(NTILES, 2), 256, DYNSM1>>>(
            p_ah, nullptr, p_w1h + (size_t)l * HID * EMB,
            b1 + (size_t)l * HID, p_hh, 256);
        if (l < NLAYERS - 1)
            gemm2_bn<0><<<GRID2, 256, DYNSM1>>>(
                p_hh, p_w2h + (size_t)l * EMB * HID, p_agg, (void*)p_h,
                p_bsum + l * EMB, p_bsq + l * EMB,
                gamma + (size_t)l * EMB, beta + (size_t)l * EMB, p_sync + l);
        else
            gemm2_bn<1><<<GRID2, 256, DYNSM1>>>(
                p_hh, p_w2h + (size_t)l * EMB * HID, p_agg, (void*)out,
                p_bsum + l * EMB, p_bsq + l * EMB,
                gamma + (size_t)l * EMB, beta + (size_t)l * EMB, p_sync + l);
    }
}

// round 16
// speedup vs baseline: 1.4700x; 1.0480x over previous
#include <cuda_runtime.h>
#include <cuda_fp16.h>
#include <cstdint>

#define N_NODES 50000
#define NP      50048            // padded to 391*128
#define N_EDGES 800000
#define EMB     128
#define HID     256
#define EDGE_F  16
#define NLAYERS 5
#define BN_EPS  1e-5f

// ================= device scratch (static, no allocation) =================
__device__ __half g_ah[NP * EMB];   // A (fp16): x rounded, then gather out
__device__ __half g_hh[NP * HID];   // hidden (GEMM2 A)
__device__ __half g_h[NP * EMB];    // node features (fp16)
__device__ float g_agg[NP * EMB];   // layer out (pre-BN, fp32)
__device__ __half g_wxh[EMB * EMB];            // weights: fp16, [N][K] transposed
__device__ __half g_w1h[NLAYERS * HID * EMB];
__device__ __half g_w2h[NLAYERS * EMB * HID];
__device__ float g_S[N_NODES * EDGE_F];
__device__ int   g_deg[N_NODES];
__device__ int   g_fill[N_NODES];
__device__ int   g_rowptr[N_NODES + 1];
__device__ int   g_csr_src[N_EDGES];
__device__ int   g_csr_eid[N_EDGES];
__device__ float g_bsum[NLAYERS * EMB];
__device__ float g_bsq[NLAYERS * EMB];

#define LDSM4(r0, r1, r2, r3, addr) \
    asm volatile("ldmatrix.sync.aligned.m8n8.x4.shared.b16 {%0,%1,%2,%3}, [%4];" \
                 : "=r"(r0), "=r"(r1), "=r"(r2), "=r"(r3) : "r"(addr))

#define MMA16816(d, a, b0, b1) \
    asm volatile("mma.sync.aligned.m16n8k16.row.col.f32.f16.f16.f32 " \
                 "{%0,%1,%2,%3},{%4,%5,%6,%7},{%8,%9},{%0,%1,%2,%3};" \
                 : "+f"((d)[0]), "+f"((d)[1]), "+f"((d)[2]), "+f"((d)[3]) \
                 : "r"((a)[0]), "r"((a)[1]), "r"((a)[2]), "r"((a)[3]), \
                   "r"(b0), "r"(b1))

#define CP_ASYNC16(dst, src) \
    asm volatile("cp.async.cg.shared.global [%0], [%1], 16;" :: "r"(dst), "l"(src))
#define CP_COMMIT() asm volatile("cp.async.commit_group;")
#define CP_WAIT1()  asm volatile("cp.async.wait_group 1;")
#define CP_WAIT0()  asm volatile("cp.async.wait_group 0;")

#define ACC_ROW(acc, raw) do { \
    const __half2* _p = (const __half2*)&(raw); \
    float2 _a = __half22float2(_p[0]); \
    float2 _b = __half22float2(_p[1]); \
    (acc).x += _a.x; (acc).y += _a.y; (acc).z += _b.x; (acc).w += _b.y; \
} while (0)

// ================= combined prep: zero + weight transposes + x round =================
__global__ void k_prep(const float* __restrict__ Wx, const float* __restrict__ W1,
                       const float* __restrict__ W2, const float* __restrict__ x) {
    int i = blockIdx.x * blockDim.x + threadIdx.x;
    if (i < N_NODES) { g_deg[i] = 0; g_fill[i] = 0; }
    if (i < NLAYERS * EMB) { g_bsum[i] = 0.f; g_bsq[i] = 0.f; }
    if (i < EMB * EMB) {
        int k = i / EMB, n = i - k * EMB;
        g_wxh[n * EMB + k] = __float2half_rn(Wx[i]);
    }
    if (i < NLAYERS * EMB * HID) {
        int l = i / (EMB * HID);
        int r = i - l * (EMB * HID);
        int k = r / HID, n = r - k * HID;
        g_w1h[l * EMB * HID + n * EMB + k] = __float2half_rn(W1[i]);
    }
    if (i < NLAYERS * HID * EMB) {
        int l = i / (HID * EMB);
        int r = i - l * (HID * EMB);
        int k = r / EMB, n = r - k * EMB;
        g_w2h[l * HID * EMB + n * HID + k] = __float2half_rn(W2[i]);
    }
    if (i < N_NODES * EMB / 4) {
        float4 v = __ldg(&((const float4*)x)[i]);
        size_t base = (size_t)i * 4;
        *(__half2*)&g_ah[base]     = __floats2half2_rn(v.x, v.y);
        *(__half2*)&g_ah[base + 2] = __floats2half2_rn(v.z, v.w);
    }
}

__global__ void k_hist(const int* __restrict__ ei) {
    int e = blockIdx.x * blockDim.x + threadIdx.x;
    if (e < N_EDGES) atomicAdd(&g_deg[ei[N_EDGES + e]], 1);
}
__global__ void k_scan() {
    const int NT = 1024;
    const int CH = (N_NODES + NT - 1) / NT;
    __shared__ int sh[NT];
    int t = threadIdx.x;
    int s0 = t * CH, s1 = s0 + CH;
    if (s1 > N_NODES) s1 = N_NODES;
    int s = 0;
    for (int i = s0; i < s1; i++) s += g_deg[i];
    sh[t] = s;
    __syncthreads();
    for (int off = 1; off < NT; off <<= 1) {
        int v = (t >= off) ? sh[t - off] : 0;
        __syncthreads();
        sh[t] += v;
        __syncthreads();
    }
    int run = sh[t] - s;
    for (int i = s0; i < s1; i++) { g_rowptr[i] = run; run += g_deg[i]; }
    if (t == NT - 1) g_rowptr[N_NODES] = sh[NT - 1];
}
__global__ void k_fill(const int* __restrict__ ei) {
    int e = blockIdx.x * blockDim.x + threadIdx.x;
    if (e >= N_EDGES) return;
    int src = ei[e];
    int dst = ei[N_EDGES + e];
    int pos = g_rowptr[dst] + atomicAdd(&g_fill[dst], 1);
    g_csr_src[pos] = src;
    g_csr_eid[pos] = e;
}
__global__ void k_ssum(const float* __restrict__ ea) {
    int gw = (blockIdx.x * blockDim.x + threadIdx.x) >> 5;
    int lane = threadIdx.x & 31;
    if (gw >= N_NODES || lane >= EDGE_F) return;
    int beg = g_rowptr[gw], end = g_rowptr[gw + 1];
    float s = 0.f;
    for (int e = beg; e < end; e++)
        s += ea[(size_t)g_csr_eid[e] * EDGE_F + lane];
    g_S[gw * EDGE_F + lane] = s;
}

// ================= gather / aggregate (warp per node, wide grid) =================
__global__ void __launch_bounds__(256) k_gather(const float* __restrict__ We_l,
                                                const float* __restrict__ be_l) {
    __shared__ float sWe[EDGE_F * EMB];
    for (int i = threadIdx.x; i < EDGE_F * EMB; i += blockDim.x) sWe[i] = We_l[i];
    __syncthreads();

    int gw = (blockIdx.x * blockDim.x + threadIdx.x) >> 5;
    int lane = threadIdx.x & 31;
    if (gw >= N_NODES) return;

    const float2* h2p = (const float2*)g_h;
    int beg = g_rowptr[gw], end = g_rowptr[gw + 1];

    float4 acc = make_float4(0.f, 0.f, 0.f, 0.f);
    {
        float2 raw = __ldg(&h2p[(size_t)gw * 32 + lane]);   // self loop
        ACC_ROW(acc, raw);
    }
    int e = beg;
    for (; e + 2 <= end; e += 2) {
        float2 r0 = __ldg(&h2p[(size_t)g_csr_src[e] * 32 + lane]);
        float2 r1 = __ldg(&h2p[(size_t)g_csr_src[e + 1] * 32 + lane]);
        ACC_ROW(acc, r0);
        ACC_ROW(acc, r1);
    }
    if (e < end) {
        float2 r0 = __ldg(&h2p[(size_t)g_csr_src[e] * 32 + lane]);
        ACC_ROW(acc, r0);
    }

    int deg = end - beg;
#pragma unroll
    for (int k = 0; k < EDGE_F; k++) {
        float s = g_S[gw * EDGE_F + k];
        float4 w = *(const float4*)&sWe[k * EMB + lane * 4];
        acc.x += s * w.x; acc.y += s * w.y;
        acc.z += s * w.z; acc.w += s * w.w;
    }
    float c = (float)(deg + 1);
    float4 bb = __ldg(&((const float4*)be_l)[lane]);
    acc.x += c * bb.x; acc.y += c * bb.y;
    acc.z += c * bb.z; acc.w += c * bb.w;

    size_t base = (size_t)gw * EMB + lane * 4;
    *(__half2*)&g_ah[base]     = __floats2half2_rn(acc.x, acc.y);
    *(__half2*)&g_ah[base + 2] = __floats2half2_rn(acc.z, acc.w);
}

// ================= mma.sync fp16 GEMM (single-term A) =================
// C = Ah @ Bh, fp32 accum. 256 threads = 8 warps (4m x 2n), warp tile 32x64,
// K chunks of 64, 2-stage cp.async pipeline. Per stage smem: Ah | B.
// MODE 0: oh = fp16(C + bias).
// MODE 1: oh = fp16(relu(C + bias)).
// MODE 2: outf = C (bias cancels in BN) + fused BN stats -> bnsum/bnsq.
template <int KTOT, int MODE>
__global__ void __launch_bounds__(256, 2) mma_gemm(
    const __half* __restrict__ Ah, const __half* __restrict__ Bh,
    const float* __restrict__ bias,
    float* __restrict__ outf,
    __half* __restrict__ oh, int Nc,
    float* __restrict__ bnsum, float* __restrict__ bnsq)
{
    extern __shared__ __align__(16) char dynsm[];
    const uint32_t REG = 18432;           // 128 rows * 144B
    const uint32_t BUFSTRIDE = 2 * REG;   // Ah | B
    uint32_t sbase = (uint32_t)__cvta_generic_to_shared(dynsm);
    __shared__ float ssum[128];
    __shared__ float ssq[128];

    int tid = threadIdx.x, lane = tid & 31, wid = tid >> 5;
    int wm = wid & 3, wn = wid >> 2;
    size_t row0 = (size_t)blockIdx.x * 128;
    int col0 = blockIdx.y * 128;

    if (MODE == 2 && tid < 128) { ssum[tid] = 0.f; ssq[tid] = 0.f; }

    const __half* Abh = Ah + row0 * KTOT;
    const __half* Bbh = Bh + (size_t)col0 * KTOT;

    float d[2][8][4];
#pragma unroll
    for (int i = 0; i < 2; i++)
#pragma unroll
        for (int j = 0; j < 8; j++)
#pragma unroll
            for (int k = 0; k < 4; k++) d[i][j][k] = 0.f;

    int a_row = wm * 32 + (lane & 7) + ((lane >> 3) & 1) * 8;
    int a_col = ((lane >> 4) & 1) * 8;
    uint32_t a_off = (uint32_t)(a_row * 72 + a_col) * 2;
    int b_row = wn * 64 + (lane & 7) + ((lane >> 4) & 1) * 8;
    int b_col = ((lane >> 3) & 1) * 8;
    uint32_t b_off = (uint32_t)(b_row * 72 + b_col) * 2;

    const int NCH = KTOT / 64;

#define ISSUE_CHUNK(CH, BUF) do { \
    int _kc = (CH); \
    uint32_t _s = sbase + (uint32_t)(BUF) * BUFSTRIDE; \
    _Pragma("unroll") \
    for (int _it = 0; _it < 4; _it++) { \
        int _idx = tid + _it * 256; \
        int _r = _idx >> 3, _c8 = _idx & 7; \
        uint32_t _soff = (uint32_t)(_r * 144 + _c8 * 16); \
        size_t _goff = (size_t)_r * KTOT + _kc * 64 + _c8 * 8; \
        CP_ASYNC16(_s + _soff,       Abh + _goff); \
        CP_ASYNC16(_s + REG + _soff, Bbh + _goff); \
    } \
    CP_COMMIT(); \
} while (0)

    ISSUE_CHUNK(0, 0);
    for (int ch = 0; ch < NCH; ch++) {
        if (ch + 1 < NCH) {
            ISSUE_CHUNK(ch + 1, (ch + 1) & 1);
            CP_WAIT1();
        } else {
            CP_WAIT0();
        }
        __syncthreads();
        uint32_t bufb = sbase + (uint32_t)(ch & 1) * BUFSTRIDE;
#pragma unroll
        for (int ks = 0; ks < 4; ks++) {
            uint32_t a[2][4];
            uint32_t ad = bufb + a_off + (uint32_t)(ks * 32);
            LDSM4(a[0][0], a[0][1], a[0][2], a[0][3], ad);
            LDSM4(a[1][0], a[1][1], a[1][2], a[1][3], ad + 16 * 144);
#pragma unroll
            for (int g = 0; g < 4; g++) {
                uint32_t b0, b1, b2, b3;
                uint32_t bd = bufb + REG + b_off + (uint32_t)(g * 16 * 144 + ks * 32);
                LDSM4(b0, b1, b2, b3, bd);
                MMA16816(d[0][2 * g],     a[0], b0, b1);
                MMA16816(d[1][2 * g],     a[1], b0, b1);
                MMA16816(d[0][2 * g + 1], a[0], b2, b3);
                MMA16816(d[1][2 * g + 1], a[1], b2, b3);
            }
        }
        __syncthreads();
    }
#undef ISSUE_CHUNK

    // ---------------- epilogue ----------------
    int r_base = (int)row0 + wm * 32 + (lane >> 2);
    int c_base = col0 + wn * 64 + 2 * (lane & 3);
#pragma unroll
    for (int mi = 0; mi < 2; mi++) {
#pragma unroll
        for (int ni = 0; ni < 8; ni++) {
            int gc = c_base + ni * 8;
            int r = r_base + mi * 16;
            if (MODE == 0) {
                float bz0 = __ldg(&bias[gc]);
                float bz1 = __ldg(&bias[gc + 1]);
                *(__half2*)&oh[(size_t)r * Nc + gc] =
                    __floats2half2_rn(d[mi][ni][0] + bz0, d[mi][ni][1] + bz1);
                *(__half2*)&oh[(size_t)(r + 8) * Nc + gc] =
                    __floats2half2_rn(d[mi][ni][2] + bz0, d[mi][ni][3] + bz1);
            } else if (MODE == 2) {
                float2 o0, o1;
                o0.x = d[mi][ni][0]; o0.y = d[mi][ni][1];
                o1.x = d[mi][ni][2]; o1.y = d[mi][ni][3];
                *(float2*)&outf[(size_t)r * Nc + gc] = o0;
                *(float2*)&outf[(size_t)(r + 8) * Nc + gc] = o1;
            } else {
                float bz0 = __ldg(&bias[gc]);
                float bz1 = __ldg(&bias[gc + 1]);
                *(__half2*)&oh[(size_t)r * Nc + gc] =
                    __floats2half2_rn(fmaxf(d[mi][ni][0] + bz0, 0.f),
                                      fmaxf(d[mi][ni][1] + bz1, 0.f));
                *(__half2*)&oh[(size_t)(r + 8) * Nc + gc] =
                    __floats2half2_rn(fmaxf(d[mi][ni][2] + bz0, 0.f),
                                      fmaxf(d[mi][ni][3] + bz1, 0.f));
            }
        }
    }

    if (MODE == 2) {
        float cs[8][2], cq[8][2];
#pragma unroll
        for (int ni = 0; ni < 8; ni++) { cs[ni][0] = cs[ni][1] = cq[ni][0] = cq[ni][1] = 0.f; }
#pragma unroll
        for (int mi = 0; mi < 2; mi++) {
            int rA = r_base + mi * 16;
            bool mA = rA < N_NODES, mB = (rA + 8) < N_NODES;
#pragma unroll
            for (int ni = 0; ni < 8; ni++) {
                float v0 = mA ? d[mi][ni][0] : 0.f;
                float v1 = mA ? d[mi][ni][1] : 0.f;
                float v2 = mB ? d[mi][ni][2] : 0.f;
                float v3 = mB ? d[mi][ni][3] : 0.f;
                cs[ni][0] += v0 + v2;  cs[ni][1] += v1 + v3;
                cq[ni][0] += v0 * v0 + v2 * v2;
                cq[ni][1] += v1 * v1 + v3 * v3;
            }
        }
#pragma unroll
        for (int off = 4; off <= 16; off <<= 1) {
#pragma unroll
            for (int ni = 0; ni < 8; ni++) {
                cs[ni][0] += __shfl_xor_sync(0xFFFFFFFF, cs[ni][0], off);
                cs[ni][1] += __shfl_xor_sync(0xFFFFFFFF, cs[ni][1], off);
                cq[ni][0] += __shfl_xor_sync(0xFFFFFFFF, cq[ni][0], off);
                cq[ni][1] += __shfl_xor_sync(0xFFFFFFFF, cq[ni][1], off);
            }
        }
        if ((lane >> 2) == 0) {
            int cb = wn * 64 + 2 * lane;
#pragma unroll
            for (int ni = 0; ni < 8; ni++) {
                atomicAdd(&ssum[cb + ni * 8],     cs[ni][0]);
                atomicAdd(&ssum[cb + ni * 8 + 1], cs[ni][1]);
                atomicAdd(&ssq[cb + ni * 8],      cq[ni][0]);
                atomicAdd(&ssq[cb + ni * 8 + 1],  cq[ni][1]);
            }
        }
        __syncthreads();
        if (tid < 128) {
            atomicAdd(&bnsum[tid], ssum[tid]);
            atomicAdd(&bnsq[tid],  ssq[tid]);
        }
    }
}

// ================= BatchNorm apply =================
// HOUT=1: write fp16 h (inner layers, RELU).  HOUT=0: write fp32 out (last layer).
template <int RELU, int HOUT>
__global__ void __launch_bounds__(256) k_bnapply(
    const float* __restrict__ H, void* __restrict__ O,
    const float* __restrict__ bnsum, const float* __restrict__ bnsq,
    const float* __restrict__ gamma_l, const float* __restrict__ beta_l)
{
    __shared__ float s_scale[EMB];
    __shared__ float s_shift[EMB];
    if (threadIdx.x < EMB) {
        int f = threadIdx.x;
        float inv_n = 1.f / (float)N_NODES;
        float mean = __ldg(&bnsum[f]) * inv_n;
        float var = __ldg(&bnsq[f]) * inv_n - mean * mean;
        float sc = __ldg(&gamma_l[f]) * rsqrtf(var + BN_EPS);
        s_scale[f] = sc;
        s_shift[f] = __ldg(&beta_l[f]) - mean * sc;
    }
    __syncthreads();
    int idx = blockIdx.x * blockDim.x + threadIdx.x;
    if (idx >= N_NODES * 32) return;
    int c4 = idx & 31;
    float4 v = ((const float4*)H)[idx];
    float4 sc = ((const float4*)s_scale)[c4];
    float4 sh = ((const float4*)s_shift)[c4];
    float4 o;
    o.x = v.x * sc.x + sh.x;
    o.y = v.y * sc.y + sh.y;
    o.z = v.z * sc.z + sh.z;
    o.w = v.w * sc.w + sh.w;
    if (RELU) {
        o.x = fmaxf(o.x, 0.f); o.y = fmaxf(o.y, 0.f);
        o.z = fmaxf(o.z, 0.f); o.w = fmaxf(o.w, 0.f);
    }
    if (HOUT) {
        __half* O16 = (__half*)O;
        *(__half2*)&O16[(size_t)idx * 4]     = __floats2half2_rn(o.x, o.y);
        *(__half2*)&O16[(size_t)idx * 4 + 2] = __floats2half2_rn(o.z, o.w);
    } else {
        ((float4*)O)[idx] = o;
    }
}

// ================= launch =================
extern "C" void kernel_launch(void* const* d_in, const int* in_sizes, int n_in,
                              void* d_out, int out_size) {
    const float* x         = (const float*)d_in[0];
    const float* edge_attr = (const float*)d_in[1];
    const int*   ei        = (const int*)d_in[2];
    const float* Wx        = (const float*)d_in[3];
    const float* bx        = (const float*)d_in[4];
    const float* We        = (const float*)d_in[5];
    const float* be        = (const float*)d_in[6];
    const float* W1        = (const float*)d_in[7];
    const float* b1        = (const float*)d_in[8];
    const float* W2        = (const float*)d_in[9];
    const float* b2        = (const float*)d_in[10];  // unused: cancels in BN
    const float* gamma     = (const float*)d_in[11];
    const float* beta      = (const float*)d_in[12];
    float* out = (float*)d_out;
    (void)b2;

    float *p_agg, *p_bsum, *p_bsq;
    __half *p_ah, *p_hh, *p_h, *p_wxh, *p_w1h, *p_w2h;
    cudaGetSymbolAddress((void**)&p_h,    g_h);
    cudaGetSymbolAddress((void**)&p_agg,  g_agg);
    cudaGetSymbolAddress((void**)&p_bsum, g_bsum);
    cudaGetSymbolAddress((void**)&p_bsq,  g_bsq);
    cudaGetSymbolAddress((void**)&p_ah,   g_ah);
    cudaGetSymbolAddress((void**)&p_hh,   g_hh);
    cudaGetSymbolAddress((void**)&p_wxh,  g_wxh);
    cudaGetSymbolAddress((void**)&p_w1h,  g_w1h);
    cudaGetSymbolAddress((void**)&p_w2h,  g_w2h);

    const int DYNSM1 = 2 * 2 * 18432;  // 73728 (2 stages x (Ah|B))
    cudaFuncSetAttribute(mma_gemm<128, 0>, cudaFuncAttributeMaxDynamicSharedMemorySize, DYNSM1);
    cudaFuncSetAttribute(mma_gemm<128, 1>, cudaFuncAttributeMaxDynamicSharedMemorySize, DYNSM1);
    cudaFuncSetAttribute(mma_gemm<256, 2>, cudaFuncAttributeMaxDynamicSharedMemorySize, DYNSM1);

    const int NTILES = NP / 128;  // 391
    const int PREPN = N_NODES * EMB / 4;  // 1.6M threads covers all prep ranges

    // Launch order: #4 = mma_gemm (GEMM0) for the ncu capture slot.
    k_prep<<<(PREPN + 255) / 256, 256>>>(Wx, W1, W2, x);                        // 1
    k_hist<<<(N_EDGES + 255) / 256, 256>>>(ei);                                 // 2
    k_scan<<<1, 1024>>>();                                                      // 3
    mma_gemm<128, 0><<<dim3(NTILES, 1), 256, DYNSM1>>>(p_ah, p_wxh,             // 4
        bx, nullptr, p_h, 128, nullptr, nullptr);
    k_fill<<<(N_EDGES + 255) / 256, 256>>>(ei);                                 // 5
    k_ssum<<<(N_NODES * 32 + 255) / 256, 256>>>(edge_attr);                     // 6

    for (int l = 0; l < NLAYERS; l++) {
        k_gather<<<(N_NODES * 32 + 255) / 256, 256>>>(We + (size_t)l * EDGE_F * EMB,
                                                      be + (size_t)l * EMB);
        mma_gemm<128, 1><<<dim3(NTILES, 2), 256, DYNSM1>>>(
            p_ah, p_w1h + (size_t)l * HID * EMB,
            b1 + (size_t)l * HID, nullptr, p_hh, 256, nullptr, nullptr);
        mma_gemm<256, 2><<<dim3(NTILES, 1), 256, DYNSM1>>>(
            p_hh, p_w2h + (size_t)l * EMB * HID,
            nullptr, p_agg, nullptr, 128,
            p_bsum + l * EMB, p_bsq + l * EMB);
        if (l < NLAYERS - 1)
            k_bnapply<1, 1><<<(N_NODES * 32 + 255) / 256, 256>>>(
                p_agg, (void*)p_h, p_bsum + l * EMB, p_bsq + l * EMB,
                gamma + (size_t)l * EMB, beta + (size_t)l * EMB);
        else
            k_bnapply<0, 0><<<(N_NODES * 32 + 255) / 256, 256>>>(
                p_agg, (void*)out, p_bsum + l * EMB, p_bsq + l * EMB,
                gamma + (size_t)l * EMB, beta + (size_t)l * EMB);
    }
}